// round 2
// baseline (speedup 1.0000x reference)
#include <cuda_runtime.h>
#include <math.h>
#include <stdint.h>

// PINN_Difference_RNN: out_t = x_{t-1} + [c*cos(h), c*sin(h)] - x_t
// where x_t = A x_{t-1} + g_t,  A = W_A (constant),  g_t = W_B u_t + bA + bB,
// c = speed_t * dt_t, h = heading_t.  Linear recurrence with constant A ->
// single-pass chunked scan with decoupled lookback.

#define NTHREADS 256
#define MPT 8
#define CHUNK (NTHREADS * MPT)   // 2048 elements per block
#define MAXB 8192

// Decoupled-lookback state. Separate aggregate/inclusive slots + fenced flag
// protocol (data store -> threadfence -> flag store; flag load -> threadfence
// -> data load). flag: 0=empty, 1=aggregate ready, 2=inclusive ready.
__device__ float2 g_agg[MAXB];
__device__ float2 g_inc[MAXB];
__device__ int    g_flag[MAXB];
__device__ unsigned int g_ticket;

__global__ void init_kernel(int nblocks) {
    int i = blockIdx.x * blockDim.x + threadIdx.x;
    if (i == 0) g_ticket = 0u;
    if (i < nblocks) g_flag[i] = 0;
}

__global__ __launch_bounds__(NTHREADS)
void pinn_kernel(const float* __restrict__ x0in, const float* __restrict__ u,
                 const float* __restrict__ td, const float* __restrict__ WA,
                 const float* __restrict__ bA, const float* __restrict__ WB,
                 const float* __restrict__ bB, float* __restrict__ out, int T)
{
    __shared__ float sP[9][4];              // A^(8*2^k), k=0..8  (A^8 .. A^2048)
    __shared__ unsigned s_vbid;
    __shared__ float2 s_wagg[NTHREADS / 32];
    __shared__ float2 s_wexcl[NTHREADS / 32];
    __shared__ float2 s_X0;

    const int tid = threadIdx.x;
    if (tid == 0) s_vbid = atomicAdd(&g_ticket, 1u);

    const float a00 = WA[0], a01 = WA[1], a10 = WA[2], a11 = WA[3];
    const float w00 = WB[0], w01 = WB[1], w10 = WB[2], w11 = WB[3];
    const float bs0 = bA[0] + bB[0], bs1 = bA[1] + bB[1];

    if (tid == 0) {
        // repeated squaring: A -> A^2 -> A^4 -> A^8, then A^(8*2^k)
        float m00 = a00, m01 = a01, m10 = a10, m11 = a11;
        #pragma unroll
        for (int i = 0; i < 3; i++) {
            float t00 = m00 * m00 + m01 * m10, t01 = m00 * m01 + m01 * m11;
            float t10 = m10 * m00 + m11 * m10, t11 = m10 * m01 + m11 * m11;
            m00 = t00; m01 = t01; m10 = t10; m11 = t11;
        }
        sP[0][0] = m00; sP[0][1] = m01; sP[0][2] = m10; sP[0][3] = m11;
        #pragma unroll
        for (int k = 1; k < 9; k++) {
            float t00 = m00 * m00 + m01 * m10, t01 = m00 * m01 + m01 * m11;
            float t10 = m10 * m00 + m11 * m10, t11 = m10 * m01 + m11 * m11;
            m00 = t00; m01 = t01; m10 = t10; m11 = t11;
            sP[k][0] = m00; sP[k][1] = m01; sP[k][2] = m10; sP[k][3] = m11;
        }
    }
    __syncthreads();

    const unsigned vbid = s_vbid;
    const int base = (int)(vbid * CHUNK) + tid * MPT;

    const float* __restrict__ urow0 = u;        // speed
    const float* __restrict__ urow1 = u + T;    // heading

    const bool vec_ok =
        ((((uintptr_t)u) | ((uintptr_t)td) | ((uintptr_t)out)) & 15u) == 0 &&
        (T % 4) == 0;

    // ---- load this thread's 8 elements ----
    float4 spv[2], hdv[2], dlv[2];
    if (vec_ok && base + MPT <= T) {
        const float4* p0 = (const float4*)(urow0 + base);
        const float4* p1 = (const float4*)(urow1 + base);
        const float4* pd = (const float4*)(td + base);
        spv[0] = p0[0]; spv[1] = p0[1];
        hdv[0] = p1[0]; hdv[1] = p1[1];
        dlv[0] = pd[0]; dlv[1] = pd[1];
    } else {
        float* fs = (float*)spv; float* fh = (float*)hdv; float* fd = (float*)dlv;
        #pragma unroll
        for (int i = 0; i < MPT; i++) {
            int idx = base + i;
            bool v = idx < T;
            fs[i] = v ? urow0[idx] : 0.f;
            fh[i] = v ? urow1[idx] : 0.f;
            fd[i] = v ? td[idx]    : 0.f;
        }
    }

    // ---- pass 1: per-thread serial fold (zero-init), stash g and trig forcing ----
    float g0[MPT], g1[MPT], tc0[MPT], tc1[MPT];
    float xa = 0.f, xb = 0.f;
    #pragma unroll
    for (int i = 0; i < MPT; i++) {
        float s = ((const float*)spv)[i];
        float h = ((const float*)hdv)[i];
        float d = ((const float*)dlv)[i];
        float G0 = w00 * s + w01 * h + bs0;
        float G1 = w10 * s + w11 * h + bs1;
        if (base + i >= T) { G0 = 0.f; G1 = 0.f; }
        float sn, cs;
        sincosf(h, &sn, &cs);
        float c = s * d;
        g0[i] = G0; g1[i] = G1; tc0[i] = c * cs; tc1[i] = c * sn;
        float n0 = a00 * xa + a01 * xb + G0;
        float n1 = a10 * xa + a11 * xb + G1;
        xa = n0; xb = n1;
    }

    // ---- warp Kogge-Stone scan over thread aggregates (combine matrix A^(8*2^k)) ----
    const int lane = tid & 31, warp = tid >> 5;
    float v0 = xa, v1 = xb;
    #pragma unroll
    for (int k = 0; k < 5; k++) {
        int off = 1 << k;
        float o0 = __shfl_up_sync(0xffffffffu, v0, off);
        float o1 = __shfl_up_sync(0xffffffffu, v1, off);
        if (lane >= off) {
            v0 += sP[k][0] * o0 + sP[k][1] * o1;
            v1 += sP[k][2] * o0 + sP[k][3] * o1;
        }
    }
    float e0 = __shfl_up_sync(0xffffffffu, v0, 1);
    float e1 = __shfl_up_sync(0xffffffffu, v1, 1);
    if (lane == 0) { e0 = 0.f; e1 = 0.f; }
    if (lane == 31) s_wagg[warp] = make_float2(v0, v1);
    __syncthreads();

    // ---- leader: warp-exclusive prefixes, publish, decoupled lookback ----
    if (tid == 0) {
        const float q00 = sP[5][0], q01 = sP[5][1], q10 = sP[5][2], q11 = sP[5][3]; // A^256
        float p0 = 0.f, p1 = 0.f;
        #pragma unroll
        for (int w = 0; w < NTHREADS / 32; w++) {
            float aw0 = s_wagg[w].x, aw1 = s_wagg[w].y;
            s_wexcl[w] = make_float2(p0, p1);
            float n0 = aw0 + q00 * p0 + q01 * p1;
            float n1 = aw1 + q10 * p0 + q11 * p1;
            p0 = n0; p1 = n1;
        }
        // (p0,p1) = block aggregate (zero-init scan of full chunk)

        // Block 0 publishes ONLY the inclusive flag (never flag=1), so the
        // lookback loop below can never walk past index 0.
        if (vbid != 0) {
            volatile float2* va = (volatile float2*)&g_agg[vbid];
            va->x = p0; va->y = p1;
            __threadfence();
            *(volatile int*)&g_flag[vbid] = 1;
        }

        const float c00 = sP[8][0], c01 = sP[8][1], c10 = sP[8][2], c11 = sP[8][3]; // A^2048
        float X0x, X0y;
        if (vbid == 0) {
            X0x = x0in[0]; X0y = x0in[1];
        } else {
            float acc0 = 0.f, acc1 = 0.f;
            float M00 = 1.f, M01 = 0.f, M10 = 0.f, M11 = 1.f;
            int p = (int)vbid - 1;
            for (;;) {
                int f;
                do { f = *(volatile int*)&g_flag[p]; } while (f == 0);
                __threadfence();
                if (f == 2) {
                    volatile float2* vi = (volatile float2*)&g_inc[p];
                    float sx = vi->x, sy = vi->y;
                    X0x = acc0 + M00 * sx + M01 * sy;
                    X0y = acc1 + M10 * sx + M11 * sy;
                    break;
                } else {  // f == 1, and p > 0 is guaranteed here
                    volatile float2* va2 = (volatile float2*)&g_agg[p];
                    float sx = va2->x, sy = va2->y;
                    acc0 += M00 * sx + M01 * sy;
                    acc1 += M10 * sx + M11 * sy;
                    float n00 = M00 * c00 + M01 * c10, n01 = M00 * c01 + M01 * c11;
                    float n10 = M10 * c00 + M11 * c10, n11 = M10 * c01 + M11 * c11;
                    M00 = n00; M01 = n01; M10 = n10; M11 = n11;
                    p--;
                }
            }
        }
        float i0 = p0 + c00 * X0x + c01 * X0y;
        float i1 = p1 + c10 * X0x + c11 * X0y;
        volatile float2* vinc = (volatile float2*)&g_inc[vbid];
        vinc->x = i0; vinc->y = i1;
        __threadfence();
        *(volatile int*)&g_flag[vbid] = 2;
        s_X0 = make_float2(X0x, X0y);
    }
    __syncthreads();

    // ---- per-thread start state: lane-excl + A^(8*lane)*warpExcl + A^(8*tid)*X0 ----
    float px = e0, py = e1;
    {
        float wx = s_wexcl[warp].x, wy = s_wexcl[warp].y;
        #pragma unroll
        for (int k = 0; k < 5; k++) {
            if ((lane >> k) & 1) {
                float nx = sP[k][0] * wx + sP[k][1] * wy;
                float ny = sP[k][2] * wx + sP[k][3] * wy;
                wx = nx; wy = ny;
            }
        }
        px += wx; py += wy;
        float cx = s_X0.x, cy = s_X0.y;
        #pragma unroll
        for (int k = 0; k < 8; k++) {
            if ((tid >> k) & 1) {
                float nx = sP[k][0] * cx + sP[k][1] * cy;
                float ny = sP[k][2] * cx + sP[k][3] * cy;
                cx = nx; cy = ny;
            }
        }
        px += cx; py += cy;
    }

    // ---- pass 2: replay with true start state, emit outputs ----
    float4 ov[2 * MPT / 4];
    float* o = (float*)ov;
    float ya = px, yb = py;
    #pragma unroll
    for (int i = 0; i < MPT; i++) {
        float n0 = a00 * ya + a01 * yb + g0[i];
        float n1 = a10 * ya + a11 * yb + g1[i];
        o[2 * i]     = ya + tc0[i] - n0;
        o[2 * i + 1] = yb + tc1[i] - n1;
        ya = n0; yb = n1;
    }
    if (vec_ok && base + MPT <= T) {
        float4* po = (float4*)(out + 2 * base);
        #pragma unroll
        for (int i = 0; i < 2 * MPT / 4; i++) po[i] = ov[i];
    } else {
        #pragma unroll
        for (int i = 0; i < MPT; i++) {
            int idx = base + i;
            if (idx < T) {
                out[2 * idx]     = o[2 * i];
                out[2 * idx + 1] = o[2 * i + 1];
            }
        }
    }
}

extern "C" void kernel_launch(void* const* d_in, const int* in_sizes, int n_in,
                              void* d_out, int out_size)
{
    const float* x0 = (const float*)d_in[0];
    const float* u  = (const float*)d_in[1];
    const float* td = (const float*)d_in[2];
    const float* WA = (const float*)d_in[3];
    const float* bA = (const float*)d_in[4];
    const float* WB = (const float*)d_in[5];
    const float* bB = (const float*)d_in[6];
    int T = in_sizes[2];
    int nblocks = (T + CHUNK - 1) / CHUNK;
    if (nblocks > MAXB) nblocks = MAXB;  // T=4194304 -> 2048 blocks
    init_kernel<<<(nblocks + 255) / 256, 256>>>(nblocks);
    pinn_kernel<<<nblocks, NTHREADS>>>(x0, u, td, WA, bA, WB, bB, (float*)d_out, T);
}

// round 3
// speedup vs baseline: 2.1357x; 2.1357x over previous
#include <cuda_runtime.h>
#include <math.h>
#include <stdint.h>

// PINN_Difference_RNN: out_t = x_{t-1} + [c*cos(h), c*sin(h)] - x_t
// x_t = A x_{t-1} + g_t, A = W_A const, g_t = W_B u_t + bA + bB.
// Single-pass chunked affine scan, decoupled lookback (warp-parallel).

#define NTHREADS 256
#define MPT 8
#define CHUNK (NTHREADS * MPT)   // 2048 elements per block
#define MAXB 8192
#define NMAT 14                  // sM[k] = A^(8*2^k), k=0..13 (A^8 .. A^65536)

__device__ float2 g_agg[MAXB];
__device__ float2 g_inc[MAXB];
__device__ int    g_flag[MAXB];   // 0=empty, 1=aggregate, 2=inclusive
__device__ unsigned int g_ticket;

__global__ void init_kernel(int nblocks) {
    int i = blockIdx.x * blockDim.x + threadIdx.x;
    if (i == 0) g_ticket = 0u;
    if (i < nblocks) g_flag[i] = 0;
}

__global__ __launch_bounds__(NTHREADS)
void pinn_kernel(const float* __restrict__ x0in, const float* __restrict__ u,
                 const float* __restrict__ td, const float* __restrict__ WA,
                 const float* __restrict__ bA, const float* __restrict__ WB,
                 const float* __restrict__ bB, float* __restrict__ out, int T)
{
    __shared__ float sM[NMAT][4];
    __shared__ unsigned s_vbid;
    __shared__ float2 s_wagg[NTHREADS / 32];
    __shared__ float2 s_wexcl[NTHREADS / 32];
    __shared__ float2 s_X0;

    const int tid = threadIdx.x;
    if (tid == 0) s_vbid = atomicAdd(&g_ticket, 1u);

    const float a00 = WA[0], a01 = WA[1], a10 = WA[2], a11 = WA[3];
    const float w00 = WB[0], w01 = WB[1], w10 = WB[2], w11 = WB[3];
    const float bs0 = bA[0] + bB[0], bs1 = bA[1] + bB[1];

    if (tid == 0) {
        float m00 = a00, m01 = a01, m10 = a10, m11 = a11;
        #pragma unroll
        for (int i = 0; i < 3; i++) {       // A -> A^8
            float t00 = m00*m00 + m01*m10, t01 = m00*m01 + m01*m11;
            float t10 = m10*m00 + m11*m10, t11 = m10*m01 + m11*m11;
            m00 = t00; m01 = t01; m10 = t10; m11 = t11;
        }
        sM[0][0] = m00; sM[0][1] = m01; sM[0][2] = m10; sM[0][3] = m11;
        #pragma unroll
        for (int k = 1; k < NMAT; k++) {    // A^(8*2^k)
            float t00 = m00*m00 + m01*m10, t01 = m00*m01 + m01*m11;
            float t10 = m10*m00 + m11*m10, t11 = m10*m01 + m11*m11;
            m00 = t00; m01 = t01; m10 = t10; m11 = t11;
            sM[k][0] = m00; sM[k][1] = m01; sM[k][2] = m10; sM[k][3] = m11;
        }
    }
    __syncthreads();

    const unsigned vbid = s_vbid;
    const int base = (int)(vbid * CHUNK) + tid * MPT;
    const float* __restrict__ urow0 = u;
    const float* __restrict__ urow1 = u + T;

    const bool vec_ok =
        ((((uintptr_t)u) | ((uintptr_t)td) | ((uintptr_t)out)) & 15u) == 0 &&
        (T % 4) == 0;

    // ---- load 8 elements ----
    float4 spv[2], hdv[2], dlv[2];
    if (vec_ok && base + MPT <= T) {
        const float4* p0 = (const float4*)(urow0 + base);
        const float4* p1 = (const float4*)(urow1 + base);
        const float4* pd = (const float4*)(td + base);
        spv[0] = p0[0]; spv[1] = p0[1];
        hdv[0] = p1[0]; hdv[1] = p1[1];
        dlv[0] = pd[0]; dlv[1] = pd[1];
    } else {
        float* fs = (float*)spv; float* fh = (float*)hdv; float* fd = (float*)dlv;
        #pragma unroll
        for (int i = 0; i < MPT; i++) {
            int idx = base + i;
            bool v = idx < T;
            fs[i] = v ? urow0[idx] : 0.f;
            fh[i] = v ? urow1[idx] : 0.f;
            fd[i] = v ? td[idx]    : 0.f;
        }
    }

    // ---- pass 1: serial fold (zero-init), stash forcing terms ----
    float g0[MPT], g1[MPT], tc0[MPT], tc1[MPT];
    float xa = 0.f, xb = 0.f;
    #pragma unroll
    for (int i = 0; i < MPT; i++) {
        float s = ((const float*)spv)[i];
        float h = ((const float*)hdv)[i];
        float d = ((const float*)dlv)[i];
        float G0 = w00*s + w01*h + bs0;
        float G1 = w10*s + w11*h + bs1;
        if (base + i >= T) { G0 = 0.f; G1 = 0.f; }
        float sn, cs;
        __sincosf(h, &sn, &cs);
        float c = s * d;
        g0[i] = G0; g1[i] = G1; tc0[i] = c*cs; tc1[i] = c*sn;
        float n0 = a00*xa + a01*xb + G0;
        float n1 = a10*xa + a11*xb + G1;
        xa = n0; xb = n1;
    }

    // ---- warp Kogge-Stone over thread aggregates ----
    const int lane = tid & 31, warp = tid >> 5;
    float v0 = xa, v1 = xb;
    #pragma unroll
    for (int k = 0; k < 5; k++) {
        int off = 1 << k;
        float o0 = __shfl_up_sync(0xffffffffu, v0, off);
        float o1 = __shfl_up_sync(0xffffffffu, v1, off);
        if (lane >= off) {
            v0 += sM[k][0]*o0 + sM[k][1]*o1;
            v1 += sM[k][2]*o0 + sM[k][3]*o1;
        }
    }
    float e0 = __shfl_up_sync(0xffffffffu, v0, 1);
    float e1 = __shfl_up_sync(0xffffffffu, v1, 1);
    if (lane == 0) { e0 = 0.f; e1 = 0.f; }
    if (lane == 31) s_wagg[warp] = make_float2(v0, v1);
    __syncthreads();

    // ---- warp 0: block aggregate, publish, warp-parallel lookback ----
    if (warp == 0) {
        float p0 = 0.f, p1 = 0.f;     // block aggregate (lane 0 authoritative)
        if (lane == 0) {
            const float q00 = sM[5][0], q01 = sM[5][1], q10 = sM[5][2], q11 = sM[5][3]; // A^256
            #pragma unroll
            for (int w = 0; w < NTHREADS / 32; w++) {
                float aw0 = s_wagg[w].x, aw1 = s_wagg[w].y;
                s_wexcl[w] = make_float2(p0, p1);
                float n0 = aw0 + q00*p0 + q01*p1;
                float n1 = aw1 + q10*p0 + q11*p1;
                p0 = n0; p1 = n1;
            }
            if (vbid != 0) {
                volatile float2* va = (volatile float2*)&g_agg[vbid];
                va->x = p0; va->y = p1;
                __threadfence();
                *(volatile int*)&g_flag[vbid] = 1;   // block 0 never publishes flag=1
            }
        }
        __syncwarp();

        float X0x = 0.f, X0y = 0.f;
        if (vbid == 0) {
            if (lane == 0) { X0x = x0in[0]; X0y = x0in[1]; }
        } else {
            // X0 = sum_{j=0..d-1} A^(2048*j)*agg[vbid-1-j] + A^(2048*d)*inc[vbid-1-d]
            float acc0 = 0.f, acc1 = 0.f;
            // round base matrix B = A^(2048*32*round)
            float B00 = 1.f, B01 = 0.f, B10 = 0.f, B11 = 1.f;
            const float s00 = sM[13][0], s01 = sM[13][1], s10 = sM[13][2], s11 = sM[13][3]; // A^65536
            for (int round = 0; ; round++) {
                int p = (int)vbid - 1 - (round * 32 + lane);
                bool active = (p >= 0);
                int f = 2;
                if (active) {
                    for (;;) {
                        f = *(volatile int*)&g_flag[p];
                        if (__all_sync(0xffffffffu, f != 0)) break;
                    }
                } else {
                    while (!__all_sync(0xffffffffu, 1)) {}
                }
                __threadfence();
                float vx = 0.f, vy = 0.f;
                if (active) {
                    if (f == 2) {
                        volatile float2* vi = (volatile float2*)&g_inc[p];
                        vx = vi->x; vy = vi->y;
                    } else {
                        volatile float2* va = (volatile float2*)&g_agg[p];
                        vx = va->x; vy = va->y;
                    }
                }
                unsigned ball = __ballot_sync(0xffffffffu, f == 2);
                int jstar = __ffs(ball) - 1;          // first inclusive (or -1)
                bool contrib = active && (jstar < 0 || lane <= jstar);
                if (contrib) {
                    // apply A^(2048*lane): bits of lane over sM[8+k] (A^(2048*2^k))
                    float cx = vx, cy = vy;
                    #pragma unroll
                    for (int k = 0; k < 5; k++) {
                        if ((lane >> k) & 1) {
                            float nx = sM[8 + k][0]*cx + sM[8 + k][1]*cy;
                            float ny = sM[8 + k][2]*cx + sM[8 + k][3]*cy;
                            cx = nx; cy = ny;
                        }
                    }
                    // apply round base B
                    float bx = B00*cx + B01*cy;
                    float by = B10*cx + B11*cy;
                    acc0 += bx; acc1 += by;
                }
                if (jstar >= 0) break;
                // B *= A^65536
                float n00 = B00*s00 + B01*s10, n01 = B00*s01 + B01*s11;
                float n10 = B10*s00 + B11*s10, n11 = B10*s01 + B11*s11;
                B00 = n00; B01 = n01; B10 = n10; B11 = n11;
            }
            // warp sum
            #pragma unroll
            for (int off = 16; off > 0; off >>= 1) {
                acc0 += __shfl_xor_sync(0xffffffffu, acc0, off);
                acc1 += __shfl_xor_sync(0xffffffffu, acc1, off);
            }
            X0x = acc0; X0y = acc1;
        }
        if (lane == 0) {
            const float c00 = sM[8][0], c01 = sM[8][1], c10 = sM[8][2], c11 = sM[8][3]; // A^2048
            float i0 = p0 + c00*X0x + c01*X0y;
            float i1 = p1 + c10*X0x + c11*X0y;
            volatile float2* vinc = (volatile float2*)&g_inc[vbid];
            vinc->x = i0; vinc->y = i1;
            __threadfence();
            *(volatile int*)&g_flag[vbid] = 2;
            s_X0 = make_float2(X0x, X0y);
        }
    }
    __syncthreads();

    // ---- per-thread start state ----
    float px = e0, py = e1;
    {
        float wx = s_wexcl[warp].x, wy = s_wexcl[warp].y;
        #pragma unroll
        for (int k = 0; k < 5; k++) {
            if ((lane >> k) & 1) {
                float nx = sM[k][0]*wx + sM[k][1]*wy;
                float ny = sM[k][2]*wx + sM[k][3]*wy;
                wx = nx; wy = ny;
            }
        }
        px += wx; py += wy;
        float cx = s_X0.x, cy = s_X0.y;
        #pragma unroll
        for (int k = 0; k < 8; k++) {
            if ((tid >> k) & 1) {
                float nx = sM[k][0]*cx + sM[k][1]*cy;
                float ny = sM[k][2]*cx + sM[k][3]*cy;
                cx = nx; cy = ny;
            }
        }
        px += cx; py += cy;
    }

    // ---- pass 2: replay, emit ----
    float4 ov[2 * MPT / 4];
    float* o = (float*)ov;
    float ya = px, yb = py;
    #pragma unroll
    for (int i = 0; i < MPT; i++) {
        float n0 = a00*ya + a01*yb + g0[i];
        float n1 = a10*ya + a11*yb + g1[i];
        o[2*i]     = ya + tc0[i] - n0;
        o[2*i + 1] = yb + tc1[i] - n1;
        ya = n0; yb = n1;
    }
    if (vec_ok && base + MPT <= T) {
        float4* po = (float4*)(out + 2 * base);
        #pragma unroll
        for (int i = 0; i < 2 * MPT / 4; i++) po[i] = ov[i];
    } else {
        #pragma unroll
        for (int i = 0; i < MPT; i++) {
            int idx = base + i;
            if (idx < T) {
                out[2*idx]     = o[2*i];
                out[2*idx + 1] = o[2*i + 1];
            }
        }
    }
}

extern "C" void kernel_launch(void* const* d_in, const int* in_sizes, int n_in,
                              void* d_out, int out_size)
{
    const float* x0 = (const float*)d_in[0];
    const float* u  = (const float*)d_in[1];
    const float* td = (const float*)d_in[2];
    const float* WA = (const float*)d_in[3];
    const float* bA = (const float*)d_in[4];
    const float* WB = (const float*)d_in[5];
    const float* bB = (const float*)d_in[6];
    int T = in_sizes[2];
    int nblocks = (T + CHUNK - 1) / CHUNK;
    if (nblocks > MAXB) nblocks = MAXB;  // T=4194304 -> 2048 blocks
    init_kernel<<<(nblocks + 255) / 256, 256>>>(nblocks);
    pinn_kernel<<<nblocks, NTHREADS>>>(x0, u, td, WA, bA, WB, bB, (float*)d_out, T);
}

// round 6
// speedup vs baseline: 2.7601x; 1.2924x over previous
#include <cuda_runtime.h>
#include <math.h>
#include <stdint.h>

// PINN_Difference_RNN: out_t = x_{t-1} + [c*cos(h), c*sin(h)] - x_t
// x_t = A x_{t-1} + g_t, A = W_A const, g_t = W_B u_t + bA + bB.
// Single-pass chunked affine scan, decoupled lookback (warp-parallel).
// Single-wave config: 512 blocks x 256 threads x 32 elems; pass 2 re-reads
// inputs from L2 instead of stashing per-element state in registers.

#define NTHREADS 256
#define MPT 32
#define CHUNK (NTHREADS * MPT)   // 8192 elements per block
#define MAXB 4096
#define NMAT 14                  // sM[k] = A^(32*2^k), k=0..13

__device__ float2 g_agg[MAXB];
__device__ float2 g_inc[MAXB];
__device__ int    g_flag[MAXB];   // 0=empty, 1=aggregate, 2=inclusive
__device__ unsigned int g_ticket;

__global__ void init_kernel(int nblocks) {
    int i = blockIdx.x * blockDim.x + threadIdx.x;
    if (i == 0) g_ticket = 0u;
    if (i < nblocks) g_flag[i] = 0;
}

__global__ __launch_bounds__(NTHREADS, 4)
void pinn_kernel(const float* __restrict__ x0in, const float* __restrict__ u,
                 const float* __restrict__ td, const float* __restrict__ WA,
                 const float* __restrict__ bA, const float* __restrict__ WB,
                 const float* __restrict__ bB, float* __restrict__ out, int T)
{
    __shared__ float sM[NMAT][4];
    __shared__ unsigned s_vbid;
    __shared__ float2 s_wagg[NTHREADS / 32];
    __shared__ float2 s_wexcl[NTHREADS / 32];
    __shared__ float2 s_X0;

    const int tid = threadIdx.x;
    if (tid == 0) s_vbid = atomicAdd(&g_ticket, 1u);

    const float a00 = WA[0], a01 = WA[1], a10 = WA[2], a11 = WA[3];
    const float w00 = WB[0], w01 = WB[1], w10 = WB[2], w11 = WB[3];
    const float bs0 = bA[0] + bB[0], bs1 = bA[1] + bB[1];

    if (tid == 0) {
        float m00 = a00, m01 = a01, m10 = a10, m11 = a11;
        #pragma unroll
        for (int i = 0; i < 5; i++) {       // A -> A^32
            float t00 = m00*m00 + m01*m10, t01 = m00*m01 + m01*m11;
            float t10 = m10*m00 + m11*m10, t11 = m10*m01 + m11*m11;
            m00 = t00; m01 = t01; m10 = t10; m11 = t11;
        }
        sM[0][0] = m00; sM[0][1] = m01; sM[0][2] = m10; sM[0][3] = m11;
        #pragma unroll
        for (int k = 1; k < NMAT; k++) {    // A^(32*2^k)
            float t00 = m00*m00 + m01*m10, t01 = m00*m01 + m01*m11;
            float t10 = m10*m00 + m11*m10, t11 = m10*m01 + m11*m11;
            m00 = t00; m01 = t01; m10 = t10; m11 = t11;
            sM[k][0] = m00; sM[k][1] = m01; sM[k][2] = m10; sM[k][3] = m11;
        }
    }
    __syncthreads();

    const unsigned vbid = s_vbid;
    const int base = (int)(vbid * CHUNK) + tid * MPT;
    const float* __restrict__ urow0 = u;        // speed
    const float* __restrict__ urow1 = u + T;    // heading

    const bool vec_ok =
        ((((uintptr_t)u) | ((uintptr_t)td) | ((uintptr_t)out)) & 15u) == 0 &&
        (T % 4) == 0;
    const bool full = vec_ok && (base + MPT <= T);

    // ---- pass 1: aggregate fold over 32 elems (reads only u; no dt/trig) ----
    float xa = 0.f, xb = 0.f;
    if (full) {
        const float4* p0 = (const float4*)(urow0 + base);
        const float4* p1 = (const float4*)(urow1 + base);
        #pragma unroll
        for (int it = 0; it < MPT / 4; it++) {
            float4 sv = p0[it];
            float4 hv = p1[it];
            #pragma unroll
            for (int j = 0; j < 4; j++) {
                float s = (&sv.x)[j], h = (&hv.x)[j];
                float G0 = w00*s + w01*h + bs0;
                float G1 = w10*s + w11*h + bs1;
                float n0 = a00*xa + a01*xb + G0;
                float n1 = a10*xa + a11*xb + G1;
                xa = n0; xb = n1;
            }
        }
    } else {
        #pragma unroll 4
        for (int i = 0; i < MPT; i++) {
            int idx = base + i;
            float s = 0.f, h = 0.f;
            bool v = idx < T;
            if (v) { s = urow0[idx]; h = urow1[idx]; }
            float G0 = v ? (w00*s + w01*h + bs0) : 0.f;
            float G1 = v ? (w10*s + w11*h + bs1) : 0.f;
            float n0 = a00*xa + a01*xb + G0;
            float n1 = a10*xa + a11*xb + G1;
            xa = n0; xb = n1;
        }
    }

    // ---- warp Kogge-Stone over thread aggregates (units of 32 elems) ----
    const int lane = tid & 31, warp = tid >> 5;
    float v0 = xa, v1 = xb;
    #pragma unroll
    for (int k = 0; k < 5; k++) {
        int off = 1 << k;
        float o0 = __shfl_up_sync(0xffffffffu, v0, off);
        float o1 = __shfl_up_sync(0xffffffffu, v1, off);
        if (lane >= off) {
            v0 += sM[k][0]*o0 + sM[k][1]*o1;
            v1 += sM[k][2]*o0 + sM[k][3]*o1;
        }
    }
    float e0 = __shfl_up_sync(0xffffffffu, v0, 1);
    float e1 = __shfl_up_sync(0xffffffffu, v1, 1);
    if (lane == 0) { e0 = 0.f; e1 = 0.f; }
    if (lane == 31) s_wagg[warp] = make_float2(v0, v1);
    __syncthreads();

    // ---- warp 0: block aggregate, publish, warp-parallel lookback ----
    if (warp == 0) {
        float p0 = 0.f, p1 = 0.f;
        if (lane == 0) {
            const float q00 = sM[5][0], q01 = sM[5][1], q10 = sM[5][2], q11 = sM[5][3]; // A^1024
            #pragma unroll
            for (int w = 0; w < NTHREADS / 32; w++) {
                float aw0 = s_wagg[w].x, aw1 = s_wagg[w].y;
                s_wexcl[w] = make_float2(p0, p1);
                float n0 = aw0 + q00*p0 + q01*p1;
                float n1 = aw1 + q10*p0 + q11*p1;
                p0 = n0; p1 = n1;
            }
            if (vbid != 0) {
                volatile float2* va = (volatile float2*)&g_agg[vbid];
                va->x = p0; va->y = p1;
                __threadfence();
                *(volatile int*)&g_flag[vbid] = 1;   // block 0 never publishes flag=1
            }
        }
        __syncwarp();

        float X0x = 0.f, X0y = 0.f;
        if (vbid == 0) {
            if (lane == 0) { X0x = x0in[0]; X0y = x0in[1]; }
        } else {
            float acc0 = 0.f, acc1 = 0.f;
            float B00 = 1.f, B01 = 0.f, B10 = 0.f, B11 = 1.f;
            const float s00 = sM[13][0], s01 = sM[13][1], s10 = sM[13][2], s11 = sM[13][3]; // A^(8192*32)
            for (int round = 0; ; round++) {
                int p = (int)vbid - 1 - (round * 32 + lane);
                bool active = (p >= 0);
                // Uniform poll loop: every lane executes the same __all_sync
                // sequence (inactive lanes report f=2), so the warp converges.
                int f;
                for (;;) {
                    f = active ? *(volatile int*)&g_flag[p] : 2;
                    if (__all_sync(0xffffffffu, f != 0)) break;
                }
                __threadfence();
                float vx = 0.f, vy = 0.f;
                if (active) {
                    if (f == 2) {
                        volatile float2* vi = (volatile float2*)&g_inc[p];
                        vx = vi->x; vy = vi->y;
                    } else {
                        volatile float2* va = (volatile float2*)&g_agg[p];
                        vx = va->x; vy = va->y;
                    }
                }
                unsigned ball = __ballot_sync(0xffffffffu, active && f == 2);
                int jstar = __ffs(ball) - 1;   // nearest inclusive lane (or -1)
                bool contrib = active && (jstar < 0 || lane <= jstar);
                if (contrib) {
                    float cx = vx, cy = vy;
                    #pragma unroll
                    for (int k = 0; k < 5; k++) {     // A^(8192*lane): sM[8+k] = A^(8192*2^k)
                        if ((lane >> k) & 1) {
                            float nx = sM[8 + k][0]*cx + sM[8 + k][1]*cy;
                            float ny = sM[8 + k][2]*cx + sM[8 + k][3]*cy;
                            cx = nx; cy = ny;
                        }
                    }
                    float bx = B00*cx + B01*cy;
                    float by = B10*cx + B11*cy;
                    acc0 += bx; acc1 += by;
                }
                if (jstar >= 0) break;
                float n00 = B00*s00 + B01*s10, n01 = B00*s01 + B01*s11;
                float n10 = B10*s00 + B11*s10, n11 = B10*s01 + B11*s11;
                B00 = n00; B01 = n01; B10 = n10; B11 = n11;
            }
            #pragma unroll
            for (int off = 16; off > 0; off >>= 1) {
                acc0 += __shfl_xor_sync(0xffffffffu, acc0, off);
                acc1 += __shfl_xor_sync(0xffffffffu, acc1, off);
            }
            X0x = acc0; X0y = acc1;
        }
        if (lane == 0) {
            const float c00 = sM[8][0], c01 = sM[8][1], c10 = sM[8][2], c11 = sM[8][3]; // A^8192
            float i0 = p0 + c00*X0x + c01*X0y;
            float i1 = p1 + c10*X0x + c11*X0y;
            volatile float2* vinc = (volatile float2*)&g_inc[vbid];
            vinc->x = i0; vinc->y = i1;
            __threadfence();
            *(volatile int*)&g_flag[vbid] = 2;
            s_X0 = make_float2(X0x, X0y);
        }
    }
    __syncthreads();

    // ---- per-thread start state: e + A^(32*lane)*warpExcl + A^(32*tid)*X0 ----
    float px = e0, py = e1;
    {
        float wx = s_wexcl[warp].x, wy = s_wexcl[warp].y;
        #pragma unroll
        for (int k = 0; k < 5; k++) {                 // A^(32*lane)
            if ((lane >> k) & 1) {
                float nx = sM[k][0]*wx + sM[k][1]*wy;
                float ny = sM[k][2]*wx + sM[k][3]*wy;
                wx = nx; wy = ny;
            }
        }
        px += wx; py += wy;
        float cx = s_X0.x, cy = s_X0.y;
        #pragma unroll
        for (int k = 0; k < 8; k++) {                 // A^(32*tid), tid<256
            if ((tid >> k) & 1) {
                float nx = sM[k][0]*cx + sM[k][1]*cy;
                float ny = sM[k][2]*cx + sM[k][3]*cy;
                cx = nx; cy = ny;
            }
        }
        px += cx; py += cy;
    }

    // ---- pass 2: re-read inputs (L2-hot), replay, emit ----
    float ya = px, yb = py;
    if (full) {
        const float4* p0 = (const float4*)(urow0 + base);
        const float4* p1 = (const float4*)(urow1 + base);
        const float4* pd = (const float4*)(td + base);
        float4* po = (float4*)(out + 2 * base);
        #pragma unroll
        for (int it = 0; it < MPT / 4; it++) {
            float4 sv = p0[it];
            float4 hv = p1[it];
            float4 dv = pd[it];
            float4 oA, oB;
            #pragma unroll
            for (int j = 0; j < 4; j++) {
                float s = (&sv.x)[j], h = (&hv.x)[j], d = (&dv.x)[j];
                float G0 = w00*s + w01*h + bs0;
                float G1 = w10*s + w11*h + bs1;
                float sn, cs;
                __sincosf(h, &sn, &cs);
                float c = s * d;
                float n0 = a00*ya + a01*yb + G0;
                float n1 = a10*ya + a11*yb + G1;
                float r0 = ya + c*cs - n0;
                float r1 = yb + c*sn - n1;
                if (j == 0) { oA.x = r0; oA.y = r1; }
                else if (j == 1) { oA.z = r0; oA.w = r1; }
                else if (j == 2) { oB.x = r0; oB.y = r1; }
                else { oB.z = r0; oB.w = r1; }
                ya = n0; yb = n1;
            }
            po[2*it]     = oA;
            po[2*it + 1] = oB;
        }
    } else {
        for (int i = 0; i < MPT; i++) {
            int idx = base + i;
            if (idx >= T) break;
            float s = urow0[idx], h = urow1[idx], d = td[idx];
            float G0 = w00*s + w01*h + bs0;
            float G1 = w10*s + w11*h + bs1;
            float sn, cs;
            __sincosf(h, &sn, &cs);
            float c = s * d;
            float n0 = a00*ya + a01*yb + G0;
            float n1 = a10*ya + a11*yb + G1;
            out[2*idx]     = ya + c*cs - n0;
            out[2*idx + 1] = yb + c*sn - n1;
            ya = n0; yb = n1;
        }
    }
}

extern "C" void kernel_launch(void* const* d_in, const int* in_sizes, int n_in,
                              void* d_out, int out_size)
{
    const float* x0 = (const float*)d_in[0];
    const float* u  = (const float*)d_in[1];
    const float* td = (const float*)d_in[2];
    const float* WA = (const float*)d_in[3];
    const float* bA = (const float*)d_in[4];
    const float* WB = (const float*)d_in[5];
    const float* bB = (const float*)d_in[6];
    int T = in_sizes[2];
    int nblocks = (T + CHUNK - 1) / CHUNK;
    if (nblocks > MAXB) nblocks = MAXB;  // T=4194304 -> 512 blocks
    init_kernel<<<(nblocks + 255) / 256, 256>>>(nblocks);
    pinn_kernel<<<nblocks, NTHREADS>>>(x0, u, td, WA, bA, WB, bB, (float*)d_out, T);
}

// round 8
// speedup vs baseline: 4.9518x; 1.7941x over previous
#include <cuda_runtime.h>
#include <math.h>
#include <stdint.h>

// PINN_Difference_RNN: out_t = x_{t-1} + [c*cos(h), c*sin(h)] - x_t
// x_t = A x_{t-1} + g_t, A = W_A const, g_t = W_B u_t + bA + bB.
// 3-kernel split affine scan (no inter-block waits):
//   K1: per-chunk aggregates (reads u)       -> g_agg
//   K2: 1-block scan of aggregates + x0      -> g_exc (per-chunk start state)
//   K3: intra-chunk scan + output emit (u L2-hot, td+out streamed)

#define NT 256
#define MPT 8
#define CHUNK (NT * MPT)     // 2048 elements per chunk
#define MAXB 4096

__device__ float2 g_agg[MAXB];
__device__ float2 g_exc[MAXB];

// ---------- helpers ----------
__device__ __forceinline__ void mat_sq(float& m00, float& m01, float& m10, float& m11) {
    float t00 = m00*m00 + m01*m10, t01 = m00*m01 + m01*m11;
    float t10 = m10*m00 + m11*m10, t11 = m10*m01 + m11*m11;
    m00 = t00; m01 = t01; m10 = t10; m11 = t11;
}

// ================= K1: per-chunk aggregate =================
__global__ __launch_bounds__(NT)
void k1_aggregate(const float* __restrict__ u, const float* __restrict__ WA,
                  const float* __restrict__ bA, const float* __restrict__ WB,
                  const float* __restrict__ bB, int T)
{
    __shared__ float sP[6][4];      // A^(8*2^k), k=0..5 (A^8..A^256)
    __shared__ float2 s_wagg[NT / 32];

    const int tid = threadIdx.x;
    const float a00 = WA[0], a01 = WA[1], a10 = WA[2], a11 = WA[3];
    const float w00 = WB[0], w01 = WB[1], w10 = WB[2], w11 = WB[3];
    const float bs0 = bA[0] + bB[0], bs1 = bA[1] + bB[1];

    if (tid == 0) {
        float m00 = a00, m01 = a01, m10 = a10, m11 = a11;
        #pragma unroll
        for (int i = 0; i < 3; i++) mat_sq(m00, m01, m10, m11);   // A^8
        sP[0][0]=m00; sP[0][1]=m01; sP[0][2]=m10; sP[0][3]=m11;
        #pragma unroll
        for (int k = 1; k < 6; k++) {
            mat_sq(m00, m01, m10, m11);
            sP[k][0]=m00; sP[k][1]=m01; sP[k][2]=m10; sP[k][3]=m11;
        }
    }
    __syncthreads();

    const int bid = blockIdx.x;
    const int base = bid * CHUNK + tid * MPT;
    const float* __restrict__ urow0 = u;
    const float* __restrict__ urow1 = u + T;
    const bool vec_ok = ((((uintptr_t)u) & 15u) == 0) && (T % 4) == 0;
    const bool full = vec_ok && (base + MPT <= T);

    float xa = 0.f, xb = 0.f;
    if (full) {
        const float4* p0 = (const float4*)(urow0 + base);
        const float4* p1 = (const float4*)(urow1 + base);
        #pragma unroll
        for (int it = 0; it < MPT / 4; it++) {
            float4 sv = p0[it], hv = p1[it];
            #pragma unroll
            for (int j = 0; j < 4; j++) {
                float s = (&sv.x)[j], h = (&hv.x)[j];
                float G0 = w00*s + w01*h + bs0;
                float G1 = w10*s + w11*h + bs1;
                float n0 = a00*xa + a01*xb + G0;
                float n1 = a10*xa + a11*xb + G1;
                xa = n0; xb = n1;
            }
        }
    } else {
        #pragma unroll
        for (int i = 0; i < MPT; i++) {
            int idx = base + i;
            bool v = idx < T;
            float s = v ? urow0[idx] : 0.f;
            float h = v ? urow1[idx] : 0.f;
            float G0 = v ? (w00*s + w01*h + bs0) : 0.f;
            float G1 = v ? (w10*s + w11*h + bs1) : 0.f;
            float n0 = a00*xa + a01*xb + G0;
            float n1 = a10*xa + a11*xb + G1;
            xa = n0; xb = n1;
        }
    }

    // warp reduce (segmented combine): v_new(i) = v(i+off) + A^(8*2^k)*v(i)
    const int lane = tid & 31, warp = tid >> 5;
    float v0 = xa, v1 = xb;
    #pragma unroll
    for (int k = 0; k < 5; k++) {
        int off = 1 << k;
        float o0 = __shfl_down_sync(0xffffffffu, v0, off);
        float o1 = __shfl_down_sync(0xffffffffu, v1, off);
        float n0 = o0 + sP[k][0]*v0 + sP[k][1]*v1;
        float n1 = o1 + sP[k][2]*v0 + sP[k][3]*v1;
        v0 = n0; v1 = n1;
    }
    if (lane == 0) s_wagg[warp] = make_float2(v0, v1);
    __syncthreads();
    if (tid == 0) {
        float p0 = 0.f, p1 = 0.f;
        #pragma unroll
        for (int w = 0; w < NT / 32; w++) {   // later = agg_w + A^256 * earlier
            float n0 = s_wagg[w].x + sP[5][0]*p0 + sP[5][1]*p1;
            float n1 = s_wagg[w].y + sP[5][2]*p0 + sP[5][3]*p1;
            p0 = n0; p1 = n1;
        }
        g_agg[bid] = make_float2(p0, p1);
    }
}

// ================= K2: scan chunk aggregates =================
__global__ __launch_bounds__(NT)
void k2_scan(const float* __restrict__ x0in, const float* __restrict__ WA, int nb)
{
    __shared__ float sMM[4];        // M = A^2048
    __shared__ float mm[8][4];      // M^(8*2^k), k=0..7
    __shared__ float2 s_wagg[NT / 32];
    __shared__ float2 s_wexcl[NT / 32];

    const int tid = threadIdx.x, lane = tid & 31, warp = tid >> 5;

    if (tid == 0) {
        float m00 = WA[0], m01 = WA[1], m10 = WA[2], m11 = WA[3];
        #pragma unroll
        for (int i = 0; i < 11; i++) mat_sq(m00, m01, m10, m11);   // A^2048
        sMM[0]=m00; sMM[1]=m01; sMM[2]=m10; sMM[3]=m11;
        #pragma unroll
        for (int i = 0; i < 3; i++) mat_sq(m00, m01, m10, m11);    // M^8
        mm[0][0]=m00; mm[0][1]=m01; mm[0][2]=m10; mm[0][3]=m11;
        #pragma unroll
        for (int k = 1; k < 8; k++) {
            mat_sq(m00, m01, m10, m11);
            mm[k][0]=m00; mm[k][1]=m01; mm[k][2]=m10; mm[k][3]=m11;
        }
    }
    __syncthreads();

    const float M00 = sMM[0], M01 = sMM[1], M10 = sMM[2], M11 = sMM[3];

    // thread serial fold over 8 consecutive chunk aggregates
    float2 vals[8];
    float xa = 0.f, xb = 0.f;
    #pragma unroll
    for (int j = 0; j < 8; j++) {
        int i = tid * 8 + j;
        float2 g = (i < nb) ? g_agg[i] : make_float2(0.f, 0.f);
        vals[j] = g;
        float n0 = M00*xa + M01*xb + g.x;
        float n1 = M10*xa + M11*xb + g.y;
        xa = n0; xb = n1;
    }

    // warp Kogge-Stone over thread aggregates (span 8 chunks each)
    float v0 = xa, v1 = xb;
    #pragma unroll
    for (int k = 0; k < 5; k++) {
        int off = 1 << k;
        float o0 = __shfl_up_sync(0xffffffffu, v0, off);
        float o1 = __shfl_up_sync(0xffffffffu, v1, off);
        if (lane >= off) {
            v0 += mm[k][0]*o0 + mm[k][1]*o1;
            v1 += mm[k][2]*o0 + mm[k][3]*o1;
        }
    }
    float e0 = __shfl_up_sync(0xffffffffu, v0, 1);
    float e1 = __shfl_up_sync(0xffffffffu, v1, 1);
    if (lane == 0) { e0 = 0.f; e1 = 0.f; }
    if (lane == 31) s_wagg[warp] = make_float2(v0, v1);
    __syncthreads();
    if (tid == 0) {
        float p0 = 0.f, p1 = 0.f;
        #pragma unroll
        for (int w = 0; w < NT / 32; w++) {
            s_wexcl[w] = make_float2(p0, p1);
            float n0 = s_wagg[w].x + mm[5][0]*p0 + mm[5][1]*p1;   // M^256
            float n1 = s_wagg[w].y + mm[5][2]*p0 + mm[5][3]*p1;
            p0 = n0; p1 = n1;
        }
    }
    __syncthreads();

    // thread start state = e + M^(8*lane)*wexcl + M^(8*tid)*x0
    float X0x = x0in[0], X0y = x0in[1];
    float px = e0, py = e1;
    {
        float wx = s_wexcl[warp].x, wy = s_wexcl[warp].y;
        #pragma unroll
        for (int k = 0; k < 5; k++) {
            if ((lane >> k) & 1) {
                float nx = mm[k][0]*wx + mm[k][1]*wy;
                float ny = mm[k][2]*wx + mm[k][3]*wy;
                wx = nx; wy = ny;
            }
        }
        px += wx; py += wy;
        float cx = X0x, cy = X0y;
        #pragma unroll
        for (int k = 0; k < 8; k++) {
            if ((tid >> k) & 1) {
                float nx = mm[k][0]*cx + mm[k][1]*cy;
                float ny = mm[k][2]*cx + mm[k][3]*cy;
                cx = nx; cy = ny;
            }
        }
        px += cx; py += cy;
    }

    // emit exclusive start state per chunk
    #pragma unroll
    for (int j = 0; j < 8; j++) {
        int i = tid * 8 + j;
        if (i < nb) g_exc[i] = make_float2(px, py);
        float n0 = M00*px + M01*py + vals[j].x;
        float n1 = M10*px + M11*py + vals[j].y;
        px = n0; py = n1;
    }
}

// ================= K3: intra-chunk scan + output =================
__global__ __launch_bounds__(NT, 4)
void k3_emit(const float* __restrict__ u, const float* __restrict__ td,
             const float* __restrict__ WA, const float* __restrict__ bA,
             const float* __restrict__ WB, const float* __restrict__ bB,
             float* __restrict__ out, int T)
{
    __shared__ float sP[8][4];      // A^(8*2^k), k=0..7 (A^8..A^1024)
    __shared__ float2 s_wagg[NT / 32];
    __shared__ float2 s_wexcl[NT / 32];

    const int tid = threadIdx.x;
    const float a00 = WA[0], a01 = WA[1], a10 = WA[2], a11 = WA[3];
    const float w00 = WB[0], w01 = WB[1], w10 = WB[2], w11 = WB[3];
    const float bs0 = bA[0] + bB[0], bs1 = bA[1] + bB[1];

    if (tid == 0) {
        float m00 = a00, m01 = a01, m10 = a10, m11 = a11;
        #pragma unroll
        for (int i = 0; i < 3; i++) mat_sq(m00, m01, m10, m11);   // A^8
        sP[0][0]=m00; sP[0][1]=m01; sP[0][2]=m10; sP[0][3]=m11;
        #pragma unroll
        for (int k = 1; k < 8; k++) {
            mat_sq(m00, m01, m10, m11);
            sP[k][0]=m00; sP[k][1]=m01; sP[k][2]=m10; sP[k][3]=m11;
        }
    }
    __syncthreads();

    const int bid = blockIdx.x;
    const int base = bid * CHUNK + tid * MPT;
    const float* __restrict__ urow0 = u;
    const float* __restrict__ urow1 = u + T;
    const bool vec_ok =
        ((((uintptr_t)u) | ((uintptr_t)td) | ((uintptr_t)out)) & 15u) == 0 &&
        (T % 4) == 0;
    const bool full = vec_ok && (base + MPT <= T);

    // pass 1: thread aggregate (u only; L2-hot after K1)
    float xa = 0.f, xb = 0.f;
    if (full) {
        const float4* p0 = (const float4*)(urow0 + base);
        const float4* p1 = (const float4*)(urow1 + base);
        #pragma unroll
        for (int it = 0; it < MPT / 4; it++) {
            float4 sv = p0[it], hv = p1[it];
            #pragma unroll
            for (int j = 0; j < 4; j++) {
                float s = (&sv.x)[j], h = (&hv.x)[j];
                float G0 = w00*s + w01*h + bs0;
                float G1 = w10*s + w11*h + bs1;
                float n0 = a00*xa + a01*xb + G0;
                float n1 = a10*xa + a11*xb + G1;
                xa = n0; xb = n1;
            }
        }
    } else {
        #pragma unroll
        for (int i = 0; i < MPT; i++) {
            int idx = base + i;
            bool v = idx < T;
            float s = v ? urow0[idx] : 0.f;
            float h = v ? urow1[idx] : 0.f;
            float G0 = v ? (w00*s + w01*h + bs0) : 0.f;
            float G1 = v ? (w10*s + w11*h + bs1) : 0.f;
            float n0 = a00*xa + a01*xb + G0;
            float n1 = a10*xa + a11*xb + G1;
            xa = n0; xb = n1;
        }
    }

    // warp Kogge-Stone scan
    const int lane = tid & 31, warp = tid >> 5;
    float v0 = xa, v1 = xb;
    #pragma unroll
    for (int k = 0; k < 5; k++) {
        int off = 1 << k;
        float o0 = __shfl_up_sync(0xffffffffu, v0, off);
        float o1 = __shfl_up_sync(0xffffffffu, v1, off);
        if (lane >= off) {
            v0 += sP[k][0]*o0 + sP[k][1]*o1;
            v1 += sP[k][2]*o0 + sP[k][3]*o1;
        }
    }
    float e0 = __shfl_up_sync(0xffffffffu, v0, 1);
    float e1 = __shfl_up_sync(0xffffffffu, v1, 1);
    if (lane == 0) { e0 = 0.f; e1 = 0.f; }
    if (lane == 31) s_wagg[warp] = make_float2(v0, v1);
    __syncthreads();
    if (tid == 0) {
        float p0 = 0.f, p1 = 0.f;
        #pragma unroll
        for (int w = 0; w < NT / 32; w++) {
            s_wexcl[w] = make_float2(p0, p1);
            float n0 = s_wagg[w].x + sP[5][0]*p0 + sP[5][1]*p1;   // A^256
            float n1 = s_wagg[w].y + sP[5][2]*p0 + sP[5][3]*p1;
            p0 = n0; p1 = n1;
        }
    }
    __syncthreads();

    // per-thread start = e + A^(8*lane)*wexcl + A^(8*tid)*X0
    float2 X0 = g_exc[bid];
    float px = e0, py = e1;
    {
        float wx = s_wexcl[warp].x, wy = s_wexcl[warp].y;
        #pragma unroll
        for (int k = 0; k < 5; k++) {
            if ((lane >> k) & 1) {
                float nx = sP[k][0]*wx + sP[k][1]*wy;
                float ny = sP[k][2]*wx + sP[k][3]*wy;
                wx = nx; wy = ny;
            }
        }
        px += wx; py += wy;
        float cx = X0.x, cy = X0.y;
        #pragma unroll
        for (int k = 0; k < 8; k++) {
            if ((tid >> k) & 1) {
                float nx = sP[k][0]*cx + sP[k][1]*cy;
                float ny = sP[k][2]*cx + sP[k][3]*cy;
                cx = nx; cy = ny;
            }
        }
        px += cx; py += cy;
    }

    // pass 2: re-read (L1-hot for u), replay, emit
    float ya = px, yb = py;
    if (full) {
        const float4* p0 = (const float4*)(urow0 + base);
        const float4* p1 = (const float4*)(urow1 + base);
        const float4* pd = (const float4*)(td + base);
        float4* po = (float4*)(out + 2 * base);
        #pragma unroll
        for (int it = 0; it < MPT / 4; it++) {
            float4 sv = p0[it], hv = p1[it], dv = pd[it];
            float4 oA, oB;
            #pragma unroll
            for (int j = 0; j < 4; j++) {
                float s = (&sv.x)[j], h = (&hv.x)[j], d = (&dv.x)[j];
                float G0 = w00*s + w01*h + bs0;
                float G1 = w10*s + w11*h + bs1;
                float sn, cs;
                __sincosf(h, &sn, &cs);
                float c = s * d;
                float n0 = a00*ya + a01*yb + G0;
                float n1 = a10*ya + a11*yb + G1;
                float r0 = ya + c*cs - n0;
                float r1 = yb + c*sn - n1;
                if (j == 0) { oA.x = r0; oA.y = r1; }
                else if (j == 1) { oA.z = r0; oA.w = r1; }
                else if (j == 2) { oB.x = r0; oB.y = r1; }
                else { oB.z = r0; oB.w = r1; }
                ya = n0; yb = n1;
            }
            po[2*it]     = oA;
            po[2*it + 1] = oB;
        }
    } else {
        for (int i = 0; i < MPT; i++) {
            int idx = base + i;
            if (idx >= T) break;
            float s = urow0[idx], h = urow1[idx], d = td[idx];
            float G0 = w00*s + w01*h + bs0;
            float G1 = w10*s + w11*h + bs1;
            float sn, cs;
            __sincosf(h, &sn, &cs);
            float c = s * d;
            float n0 = a00*ya + a01*yb + G0;
            float n1 = a10*ya + a11*yb + G1;
            out[2*idx]     = ya + c*cs - n0;
            out[2*idx + 1] = yb + c*sn - n1;
            ya = n0; yb = n1;
        }
    }
}

extern "C" void kernel_launch(void* const* d_in, const int* in_sizes, int n_in,
                              void* d_out, int out_size)
{
    const float* x0 = (const float*)d_in[0];
    const float* u  = (const float*)d_in[1];
    const float* td = (const float*)d_in[2];
    const float* WA = (const float*)d_in[3];
    const float* bA = (const float*)d_in[4];
    const float* WB = (const float*)d_in[5];
    const float* bB = (const float*)d_in[6];
    int T = in_sizes[2];
    int nb = (T + CHUNK - 1) / CHUNK;
    if (nb > MAXB) nb = MAXB;   // T = 4194304 -> nb = 2048
    k1_aggregate<<<nb, NT>>>(u, WA, bA, WB, bB, T);
    k2_scan<<<1, NT>>>(x0, WA, nb);
    k3_emit<<<nb, NT>>>(u, td, WA, bA, WB, bB, (float*)d_out, T);
}